// round 12
// baseline (speedup 1.0000x reference)
#include <cuda_runtime.h>
#include <cuda_bf16.h>

// ---------------------------------------------------------------------------
// Static geometry:
//   s0: t=8,  32x32 -> tokens [0,8192)      pe2d rows [0,1024)
//   s1: t=16, 16x16 -> tokens [8192,12288)  pe2d rows [1024,1280)
//   s2: t=4,  48x48 -> tokens [12288,21504) pe2d rows [1280,3584)
//   s3: t=1,  64x64 -> tokens [21504,25600) pe = weight rows directly
// Resize rows (axes symmetric): g 0..31: 64->32, 32..47: 64->16, 48..95: 64->48
// ---------------------------------------------------------------------------
#define DIM      1280
#define D4       320
#define NROWS_W  96
#define PE_ROWS  3584
#define TOKENS   25600
#define TPB      4          // tokens per add-block (all boundaries divisible by 4)
#define BAND     40         // every tap window fits in a 40-row band

__device__ float g_tmpW[64 * NROWS_W * DIM];   // [i][c][d]
__device__ float g_pe2d[PE_ROWS * DIM];

// ---------------------------------------------------------------------------
// Compile-time tap-window geometry (integer-exact; matches ceil(f - 2*inv_scale))
//   outsz=32: inv=2,   f=2r+0.5   -> lo = 2r-3            width 8
//   outsz=16: inv=4,   f=4r+1.5   -> lo = 4r-6            width 16
//   outsz=48: inv=4/3, f=(8r+1)/6 -> lo = ceil((8r-15)/6) width 6
// start clamped to [0, 64-width]; taps outside [0,64) masked BEFORE wsum.
// ---------------------------------------------------------------------------
__host__ __device__ constexpr int cdiv_ceil(int n, int d) {
    return (n >= 0) ? (n + d - 1) / d : -((-n) / d);
}
__host__ __device__ constexpr int iclamp(int v, int lo, int hi) {
    return v < lo ? lo : (v > hi ? hi : v);
}
__host__ __device__ constexpr int rowStart(int g) {
    return (g < 32) ? iclamp(2 * g - 3, 0, 56)
         : (g < 48) ? iclamp(4 * (g - 32) - 6, 0, 48)
                    : iclamp(cdiv_ceil(8 * (g - 48) - 15, 6), 0, 58);
}
__host__ __device__ constexpr int rowWidth(int g) {
    return (g < 32) ? 8 : (g < 48) ? 16 : 6;
}
// Band split: group 0 handles rows with start<=24 (loads i in [0,40)),
// group 1 handles start>=25 (loads i in [24,64)). Window always fits: width<=16.
__host__ __device__ constexpr bool inGroup(int g, int z) {
    return z == 0 ? (rowStart(g) <= 24) : (rowStart(g) >= 25);
}
__host__ __device__ constexpr int bandBase(int z) { return z * 24; }

// ---------------------------------------------------------------------------
// Compile-time weight table: exact fp64 Keys-cubic (a=-0.5), antialiased,
// column-normalized over valid taps only (same math as the R8 init kernel).
// ---------------------------------------------------------------------------
constexpr double c_abs(double x) { return x < 0.0 ? -x : x; }
constexpr double keys_cubic_c(double x) {
    return (x >= 2.0) ? 0.0
         : (x >= 1.0) ? ((-0.5 * x + 2.5) * x - 4.0) * x + 2.0
                      : ((1.5 * x - 2.5) * x) * x + 1.0;
}

struct WTable { float w[NROWS_W][16]; };

constexpr WTable make_wtable() {
    WTable t{};
    for (int o = 0; o < NROWS_W; o++) {
        int outsz = (o < 32) ? 32 : (o < 48) ? 16 : 48;
        int base  = (o < 32) ? 0  : (o < 48) ? 32 : 48;
        int r = o - base;
        double inv_scale = 64.0 / (double)outsz;          // == kernel_scale
        double ks_inv    = (double)outsz * (1.0 / 64.0);  // 1/kernel_scale
        double f = ((double)r + 0.5) * inv_scale - 0.5;
        int start = rowStart(o);
        double wv[16] = {};
        double wsum = 0.0;
        for (int k = 0; k < 16; k++) {
            int i = start + k;
            double w = (i < 64) ? keys_cubic_c(c_abs(f - (double)i) * ks_inv) : 0.0;
            wv[k] = w;
            wsum += w;
        }
        for (int k = 0; k < 16; k++)
            t.w[o][k] = (float)(wv[k] / wsum);
    }
    return t;
}

constexpr WTable WT = make_wtable();

// ---------------------------------------------------------------------------
// Template-unrolled emitters over a 40-float band; weights are immediates.
// ---------------------------------------------------------------------------
template<int G, int K, int BASE, bool Done>
struct TapB {
    static __device__ __forceinline__ float run(const float (&v)[BAND], float acc) {
        constexpr float wk = WT.w[G][K];
        constexpr int   ix = rowStart(G) - BASE + K;
        acc = fmaf(wk, v[ix], acc);
        return TapB<G, K + 1, BASE, (K + 1 >= rowWidth(G))>::run(v, acc);
    }
};
template<int G, int K, int BASE>
struct TapB<G, K, BASE, true> {
    static __device__ __forceinline__ float run(const float (&)[BAND], float acc) { return acc; }
};

// ---- W-pass: emit column C at outp[C*DIM] if C is in group Z ----
template<int C, int Z, bool DoEmit>
struct WEmit {
    static __device__ __forceinline__ void run(const float (&v)[BAND],
                                               float* __restrict__ outp) {
        outp[(size_t)C * DIM] = TapB<C, 0, bandBase(Z), false>::run(v, 0.f);
    }
};
template<int C, int Z>
struct WEmit<C, Z, false> {
    static __device__ __forceinline__ void run(const float (&)[BAND], float*) {}
};

template<int C, int Z, bool Done>
struct WColZ {
    static __device__ __forceinline__ void run(const float (&v)[BAND],
                                               float* __restrict__ outp) {
        WEmit<C, Z, inGroup(C, Z)>::run(v, outp);
        WColZ<C + 1, Z, (C + 1 >= NROWS_W)>::run(v, outp);
    }
};
template<int C, int Z>
struct WColZ<C, Z, true> {
    static __device__ __forceinline__ void run(const float (&)[BAND], float*) {}
};

// ---- H-pass: emit local row R (global g=GBASE+R) at outp[R*WS*DIM] if in group Z ----
template<int GBASE, int WS, int R, int Z, bool DoEmit>
struct HEmit {
    static __device__ __forceinline__ void run(const float (&v)[BAND],
                                               float* __restrict__ outp) {
        outp[(size_t)(R * WS) * DIM] = TapB<GBASE + R, 0, bandBase(Z), false>::run(v, 0.f);
    }
};
template<int GBASE, int WS, int R, int Z>
struct HEmit<GBASE, WS, R, Z, false> {
    static __device__ __forceinline__ void run(const float (&)[BAND], float*) {}
};

template<int GBASE, int RCNT, int WS, int R, int Z, bool Done>
struct HRowZ {
    static __device__ __forceinline__ void run(const float (&v)[BAND],
                                               float* __restrict__ outp) {
        HEmit<GBASE, WS, R, Z, inGroup(GBASE + R, Z)>::run(v, outp);
        HRowZ<GBASE, RCNT, WS, R + 1, Z, (R + 1 >= RCNT)>::run(v, outp);
    }
};
template<int GBASE, int RCNT, int WS, int R, int Z>
struct HRowZ<GBASE, RCNT, WS, R, Z, true> {
    static __device__ __forceinline__ void run(const float (&)[BAND], float*) {}
};

// ---------------------------------------------------------------------------
// Kernel 1 (W-pass): tmpW[i][c][d] = sum_k W[c][k] * weight[i][st_c+k][d]
// Block = (input row i, 128-float d-chunk, band z). Loads 40 rows, emits ~half
// the columns. Grid.z=2 doubles parallelism vs R11.
// ---------------------------------------------------------------------------
__global__ __launch_bounds__(128) void passW_kernel(const float* __restrict__ weight) {
    int i  = blockIdx.x;
    int d0 = blockIdx.y * 128;
    int z  = blockIdx.z;
    int tid = threadIdx.x;

    float v[BAND];
    const float* wrow = weight + (size_t)(i * 64 + z * 24) * DIM + d0 + tid;
    #pragma unroll
    for (int j = 0; j < BAND; j++)
        v[j] = wrow[(size_t)j * DIM];

    float* outp = g_tmpW + (size_t)i * NROWS_W * DIM + d0 + tid;
    if (z == 0) WColZ<0, 0, false>::run(v, outp);
    else        WColZ<0, 1, false>::run(v, outp);
}

// ---------------------------------------------------------------------------
// Kernel 2 (H-pass): pe2d[row(s,r,c)][d] = sum_k W[r][k] * tmpW[st_r+k][c][d]
// Block = (global resized column c, d-chunk, band z). Loads 40 tmpW rows.
// ---------------------------------------------------------------------------
__global__ __launch_bounds__(128) void passH_kernel() {
    int c  = blockIdx.x;
    int d0 = blockIdx.y * 128;
    int z  = blockIdx.z;
    int tid = threadIdx.x;

    float v[BAND];
    const float* src = g_tmpW + (size_t)c * DIM
                     + (size_t)(z * 24) * (NROWS_W * DIM) + d0 + tid;
    #pragma unroll
    for (int i = 0; i < BAND; i++)
        v[i] = src[(size_t)i * (NROWS_W * DIM)];

    if (c < 32) {
        float* outp = g_pe2d + (size_t)c * DIM + d0 + tid;
        if (z == 0) HRowZ<0, 32, 32, 0, 0, false>::run(v, outp);
        else        HRowZ<0, 32, 32, 0, 1, false>::run(v, outp);
    } else if (c < 48) {
        float* outp = g_pe2d + (size_t)(1024 + (c - 32)) * DIM + d0 + tid;
        if (z == 0) HRowZ<32, 16, 16, 0, 0, false>::run(v, outp);
        else        HRowZ<32, 16, 16, 0, 1, false>::run(v, outp);
    } else {
        float* outp = g_pe2d + (size_t)(1280 + (c - 48)) * DIM + d0 + tid;
        if (z == 0) HRowZ<48, 48, 48, 0, 0, false>::run(v, outp);
        else        HRowZ<48, 48, 48, 0, 1, false>::run(v, outp);
    }
}

// ---------------------------------------------------------------------------
// Kernel 3: out = x + pe(+tw). Block = 4 consecutive tokens x 320 threads.
// Sample/frame/tw-row are block-uniform; pe rows consecutive; tw reused 4x.
// ---------------------------------------------------------------------------
__global__ __launch_bounds__(320) void add_kernel(const float4* __restrict__ x,
                                                  const float4* __restrict__ weight,
                                                  const float4* __restrict__ tw,
                                                  float4* __restrict__ out) {
    int t0 = blockIdx.x * TPB;
    int d4 = threadIdx.x;

    const float4* pe0;
    int frame;
    if (t0 < 8192) {                        // s0: t=8, 32x32
        frame = t0 >> 10;
        pe0 = (const float4*)g_pe2d + (size_t)(t0 & 1023) * D4;
    } else if (t0 < 12288) {                // s1: t=16, 16x16
        int u = t0 - 8192;
        frame = u >> 8;
        pe0 = (const float4*)g_pe2d + (size_t)(1024 + (u & 255)) * D4;
    } else if (t0 < 21504) {                // s2: t=4, 48x48
        int u = t0 - 12288;
        frame = u / 2304;
        pe0 = (const float4*)g_pe2d + (size_t)(1280 + (u - frame * 2304)) * D4;
    } else {                                // s3: t=1, identity 64x64
        frame = -1;
        pe0 = weight + (size_t)(t0 - 21504) * D4;
    }

    size_t base = (size_t)t0 * D4 + d4;

    float4 a[TPB], b[TPB];
    #pragma unroll
    for (int j = 0; j < TPB; j++) a[j] = __ldcs(&x[base + (size_t)j * D4]);
    #pragma unroll
    for (int j = 0; j < TPB; j++) b[j] = pe0[(size_t)j * D4 + d4];

    float4 t = make_float4(0.f, 0.f, 0.f, 0.f);
    if (frame >= 0) t = tw[(size_t)frame * D4 + d4];

    #pragma unroll
    for (int j = 0; j < TPB; j++) {
        float4 r;
        r.x = a[j].x + b[j].x + t.x;
        r.y = a[j].y + b[j].y + t.y;
        r.z = a[j].z + b[j].z + t.z;
        r.w = a[j].w + b[j].w + t.w;
        __stcs(&out[base + (size_t)j * D4], r);
    }
}

// ---------------------------------------------------------------------------
extern "C" void kernel_launch(void* const* d_in, const int* in_sizes, int n_in,
                              void* d_out, int out_size) {
    const float* x      = (const float*)d_in[0];
    const float* weight = (const float*)d_in[1];
    const float* tw     = (const float*)d_in[2];
    float* out = (float*)d_out;

    passW_kernel<<<dim3(64, 10, 2), 128>>>(weight);
    passH_kernel<<<dim3(96, 10, 2), 128>>>();
    add_kernel<<<TOKENS / TPB, 320>>>((const float4*)x, (const float4*)weight,
                                      (const float4*)tw, (float4*)out);
}